// round 14
// baseline (speedup 1.0000x reference)
#include <cuda_runtime.h>
#include <cuda_bf16.h>
#include <cstdint>

#define B_    32
#define C_    128
#define H_    56
#define W_    56
#define OC_   256
#define HW_   (H_ * W_)          // 3136
#define KDIM  1152               // C*9
#define M_    (B_ * HW_)         // 100352
#define NW_   (OC_ * KDIM)       // 294912

#define HP    58                 // padded H
#define WP    58                 // padded W
#define HWP   (HP * WP)          // 3364
#define NXT_  (B_ * HWP * C_)    // 13787136  (padded NHWC)

#define BM    128
#define BN    128
#define BKW   32                 // k' per stage (one tap, 32 channels)
#define NSTAGE 36                // 9 taps * 4 channel-chunks
#define NT    256                // 8 warps

// ---- static device scratch ----
__device__ unsigned g_xt[NXT_];                 // padded NHWC packed x; halo = 0
__device__ __align__(16) unsigned g_wi[NW_];    // [oc][tap*128+c] = (b_hi | b_lo<<16)

// integer split-bf16 pack (no F2FP converts)
__device__ __forceinline__ unsigned pack_x(float f) {   // (lo | hi<<16)
    unsigned u  = __float_as_uint(f);
    unsigned hu = (u + 0x8000u) & 0xFFFF0000u;
    float fl    = f - __uint_as_float(hu);
    unsigned lo = (__float_as_uint(fl) + 0x8000u) >> 16;
    return hu | lo;
}
__device__ __forceinline__ unsigned pack_w(float f) {   // (hi | lo<<16)
    unsigned u  = __float_as_uint(f);
    unsigned hu = (u + 0x8000u) & 0xFFFF0000u;
    float fl    = f - __uint_as_float(hu);
    unsigned lo = (__float_as_uint(fl) + 0x8000u) & 0xFFFF0000u;
    return (hu >> 16) | lo;
}

// merged prep: b < B_ -> NCHW->padded-NHWC transpose slice; b == B_ -> W pack
__global__ void prep_kernel(const float* __restrict__ x,
                            const float* __restrict__ Wm) {
    const int b  = blockIdx.z;
    const int tx = threadIdx.x, ty = threadIdx.y;   // 32 x 8
    if (b < B_) {
        __shared__ unsigned t[32][33];
        const int h  = blockIdx.y;
        const int cb = (blockIdx.x >> 1) * 32;
        const int wb = (blockIdx.x & 1) * 32;
        const int w  = wb + tx;
        if (w < W_) {
#pragma unroll
            for (int i = 0; i < 4; i++) {
                int c = cb + ty + 8 * i;
                t[ty + 8 * i][tx] = pack_x(x[(((size_t)b * C_ + c) * H_ + h) * W_ + w]);
            }
        }
        __syncthreads();
#pragma unroll
        for (int i = 0; i < 4; i++) {
            int wo = wb + ty + 8 * i;
            int co = cb + tx;
            if (wo < W_)
                g_xt[(((size_t)b * HP + h + 1) * WP + wo + 1) * C_ + co] = t[tx][ty + 8 * i];
        }
    } else {
        const int tlin   = ty * 32 + tx;
        const int base   = (blockIdx.y * gridDim.x + blockIdx.x) * 256 + tlin;
        const int stride = gridDim.x * gridDim.y * 256;
        for (int j = base; j < NW_; j += stride) {
            int oc  = j / KDIM;
            int r   = j - oc * KDIM;
            int c   = r / 9;
            int tap = r - c * 9;
            g_wi[oc * KDIM + tap * 128 + c] = pack_w(Wm[j]);
        }
    }
}

// ---- helpers ----
__device__ __forceinline__ unsigned smem_u32(const void* p) {
    return (unsigned)__cvta_generic_to_shared(p);
}
__device__ __forceinline__ unsigned sw128(unsigned off) {
    return off ^ ((off >> 3) & 0x70);
}
__device__ __forceinline__ void cpa16(unsigned dst, const void* src) {
    asm volatile("cp.async.cg.shared.global [%0], [%1], 16;\n"
                 :: "r"(dst), "l"(src));
}
__device__ __forceinline__ void ldsm4(unsigned* r, unsigned addr) {
    asm volatile("ldmatrix.sync.aligned.m8n8.x4.shared.b16 {%0,%1,%2,%3}, [%4];"
                 : "=r"(r[0]), "=r"(r[1]), "=r"(r[2]), "=r"(r[3]) : "r"(addr));
}
__device__ __forceinline__ void mma16816(float* c, const unsigned* a,
                                         unsigned b0, unsigned b1) {
    asm("mma.sync.aligned.m16n8k16.row.col.f32.bf16.bf16.f32 "
        "{%0,%1,%2,%3}, {%4,%5,%6,%7}, {%8,%9}, {%0,%1,%2,%3};"
        : "+f"(c[0]), "+f"(c[1]), "+f"(c[2]), "+f"(c[3])
        : "r"(a[0]), "r"(a[1]), "r"(a[2]), "r"(a[3]), "r"(b0), "r"(b1));
}

// ---- smem layout (bytes) ----
#define SM_BIAS 0
#define SM_TILE 1024
#define T_A     0                // 128 pix * 128B = 16384
#define T_B     16384            // 128 oc * 128B = 16384
#define STG     32768
#define SMEM_TOTAL (SM_TILE + 3 * STG)   // 99328  -> 2 CTAs/SM

__global__ __launch_bounds__(NT, 2)
void conv_hmma_kernel(const float* __restrict__ bias, float* __restrict__ out) {
    extern __shared__ char smem[];
    const int tid  = threadIdx.x;
    const int lane = tid & 31;
    const int wid  = tid >> 5;
    const int m0   = blockIdx.x * BM;
    const int n0   = blockIdx.y * BN;

    ((float*)(smem + SM_BIAS))[tid] = bias[tid];   // NT == OC_

    // ---- A-producer: thread handles 4 pixels x one 16B channel-chunk ----
    const int chA = tid & 7;
    const unsigned* aptr[4];
    unsigned adst[4];
#pragma unroll
    for (int i = 0; i < 4; i++) {
        int pix  = (tid >> 3) + 32 * i;
        int p    = m0 + pix;
        int bimg = p / HW_;
        int hw   = p - bimg * HW_;
        int h    = hw / W_;
        int w    = hw - h * W_;
        aptr[i]  = g_xt + (((size_t)bimg * HP + h) * WP + w) * C_ + chA * 4;
        adst[i]  = (unsigned)(pix * 128 + chA * 16);
    }

    auto load_stage = [&](int s, int slot) {
        char* stg = smem + SM_TILE + slot * STG;
        int tap = s >> 2;
        int c0  = (s & 3) << 5;
        int kh  = tap / 3;
        int kw  = tap - 3 * kh;
        const size_t soff = ((size_t)kh * WP + kw) * C_ + c0;
        const unsigned abase_s = smem_u32(stg + T_A);
#pragma unroll
        for (int i = 0; i < 4; i++)
            cpa16(abase_s + sw128(adst[i]), aptr[i] + soff);
#pragma unroll
        for (int i = 0; i < 4; i++) {
            int q  = tid + NT * i;
            int oc = q >> 3;
            int ch = q & 7;
            const unsigned* bsrc = g_wi + (size_t)(n0 + oc) * KDIM + s * BKW + ch * 4;
            cpa16(smem_u32(stg + T_B + sw128((unsigned)(oc * 128 + ch * 16))), bsrc);
        }
        asm volatile("cp.async.commit_group;\n");
    };

    // warp tiling: 2 (M) x 4 (N) warps, warp tile 64 x 32
    const int wm = (wid & 1) * 64;
    const int wn = (wid >> 1) * 32;

    float acc[4][4][4];
#pragma unroll
    for (int a = 0; a < 4; a++)
#pragma unroll
        for (int b = 0; b < 4; b++)
#pragma unroll
            for (int cq = 0; cq < 4; cq++) acc[a][b][cq] = 0.0f;

    load_stage(0, 0);
    load_stage(1, 1);

    int slot = 0, slot2 = 2;
    for (int s = 0; s < NSTAGE; s++) {
        asm volatile("cp.async.wait_group 1;\n");
        __syncthreads();

        if (s + 2 < NSTAGE) load_stage(s + 2, slot2);
        else asm volatile("cp.async.commit_group;\n");

        char* stg = smem + SM_TILE + slot * STG;
        const unsigned abase = smem_u32(stg + T_A);
        const unsigned bbase = smem_u32(stg + T_B);

        // staggered traversal: odd warps run pp (and warp-pairs run ni) in
        // opposite order so ldsm and MMA phases interleave across the SMSP.
#pragma unroll
        for (int ppi = 0; ppi < 2; ppi++) {
            const int pp = ppi ^ (wid & 1);
            unsigned afrE[4][4], afrO[4][4];
#pragma unroll
            for (int mi = 0; mi < 4; mi++) {
                int row = wm + mi * 16 + (lane & 15);
                unsigned base = (unsigned)(row * 128 + (lane >> 4) * 16);
                ldsm4(afrE[mi], abase + sw128(base + (2 * pp + 0) * 32));
                ldsm4(afrO[mi], abase + sw128(base + (2 * pp + 1) * 32));
            }
            unsigned ahi[4][4];
#pragma unroll
            for (int mi = 0; mi < 4; mi++) {
                ahi[mi][0] = __byte_perm(afrE[mi][0], afrE[mi][2], 0x7632);
                ahi[mi][1] = __byte_perm(afrE[mi][1], afrE[mi][3], 0x7632);
                ahi[mi][2] = __byte_perm(afrO[mi][0], afrO[mi][2], 0x7632);
                ahi[mi][3] = __byte_perm(afrO[mi][1], afrO[mi][3], 0x7632);
            }
#pragma unroll
            for (int nii = 0; nii < 2; nii++) {
                const int ni = nii ^ ((wid >> 1) & 1);
                unsigned bE[4], bO[4];
                int g   = lane >> 3;
                int r   = lane & 7;
                int ocl = wn + ni * 16 + ((g & 2) ? 8 : 0) + r;
                unsigned base = (unsigned)(ocl * 128 + (g & 1) * 16);
                ldsm4(bE, bbase + sw128(base + (2 * pp + 0) * 32));
                ldsm4(bO, bbase + sw128(base + (2 * pp + 1) * 32));
                unsigned bh0 = __byte_perm(bE[0], bE[1], 0x5410);
                unsigned bh1 = __byte_perm(bO[0], bO[1], 0x5410);
                unsigned bh2 = __byte_perm(bE[2], bE[3], 0x5410);
                unsigned bh3 = __byte_perm(bO[2], bO[3], 0x5410);
#pragma unroll
                for (int mi = 0; mi < 4; mi++)
                    mma16816(acc[mi][ni * 2 + 0], afrE[mi], bE[0], bE[1]);
#pragma unroll
                for (int mi = 0; mi < 4; mi++)
                    mma16816(acc[mi][ni * 2 + 1], afrE[mi], bE[2], bE[3]);
#pragma unroll
                for (int mi = 0; mi < 4; mi++)
                    mma16816(acc[mi][ni * 2 + 0], afrO[mi], bO[0], bO[1]);
#pragma unroll
                for (int mi = 0; mi < 4; mi++)
                    mma16816(acc[mi][ni * 2 + 1], afrO[mi], bO[2], bO[3]);
#pragma unroll
                for (int mi = 0; mi < 4; mi++)
                    mma16816(acc[mi][ni * 2 + 0], ahi[mi], bh0, bh1);
#pragma unroll
                for (int mi = 0; mi < 4; mi++)
                    mma16816(acc[mi][ni * 2 + 1], ahi[mi], bh2, bh3);
            }
        }

        slot  = (slot  == 2) ? 0 : slot  + 1;
        slot2 = (slot2 == 2) ? 0 : slot2 + 1;
    }

    __syncthreads();

    // ---- epilogue: transpose through smem, coalesced float4 stores ----
    float* Cs = (float*)(smem + SM_TILE);   // [oc 128][pix 128] = 64KB
#pragma unroll
    for (int mi = 0; mi < 4; mi++)
#pragma unroll
        for (int nq = 0; nq < 4; nq++) {
            int r0 = wm + mi * 16 + (lane >> 2);
            int cb = wn + nq * 8 + (lane & 3) * 2;
            Cs[(cb + 0) * BM + r0]     = acc[mi][nq][0];
            Cs[(cb + 1) * BM + r0]     = acc[mi][nq][1];
            Cs[(cb + 0) * BM + r0 + 8] = acc[mi][nq][2];
            Cs[(cb + 1) * BM + r0 + 8] = acc[mi][nq][3];
        }
    __syncthreads();

    const float* bs = (const float*)(smem + SM_BIAS);
    for (int g = tid; g < BN * (BM / 4); g += NT) {
        int ocl  = g >> 5;
        int pixl = (g & 31) * 4;
        int pp   = m0 + pixl;
        int bi   = pp / HW_;
        int off  = pp - bi * HW_;
        int oc   = n0 + ocl;
        float4 v = *(const float4*)&Cs[ocl * BM + pixl];
        float bv = bs[oc];
        v.x += bv; v.y += bv; v.z += bv; v.w += bv;
        *(float4*)(out + (size_t)bi * OC_ * HW_ + (size_t)oc * HW_ + off) = v;
    }
}

extern "C" void kernel_launch(void* const* d_in, const int* in_sizes, int n_in,
                              void* d_out, int out_size) {
    const float* x  = (const float*)d_in[0];
    const float* Wm = (const float*)d_in[1];
    const float* bb = (const float*)d_in[2];
    float* out      = (float*)d_out;

    dim3 pgrid(8, H_, B_ + 1);             // z = B_ slice does W pack
    prep_kernel<<<pgrid, dim3(32, 8)>>>(x, Wm);

    cudaFuncSetAttribute(conv_hmma_kernel,
                         cudaFuncAttributeMaxDynamicSharedMemorySize, SMEM_TOTAL);
    dim3 grid(M_ / BM, OC_ / BN);   // 784 x 2
    conv_hmma_kernel<<<grid, NT, SMEM_TOTAL>>>(bb, out);
}

// round 15
// speedup vs baseline: 1.7332x; 1.7332x over previous
#include <cuda_runtime.h>
#include <cuda_bf16.h>
#include <cstdint>

#define B_    32
#define C_    128
#define H_    56
#define W_    56
#define OC_   256
#define HW_   (H_ * W_)          // 3136
#define KDIM  1152               // C*9
#define M_    (B_ * HW_)         // 100352
#define NW_   (OC_ * KDIM)       // 294912

#define HP    58                 // padded H
#define WP    58                 // padded W
#define HWP   (HP * WP)          // 3364
#define NXT_  (B_ * HWP * C_)    // 13787136  (padded NHWC)

#define BM    128
#define BN    128
#define BKW   32                 // k' per stage (one tap, 32 channels)
#define NSTAGE 36                // 9 taps * 4 channel-chunks
#define NT    256                // 8 warps

// ---- static device scratch ----
__device__ unsigned g_xt[NXT_];                 // padded NHWC packed x; halo = 0
__device__ __align__(16) unsigned g_wi[NW_];    // [oc][tap*128+c] = (b_hi | b_lo<<16)

// integer split-bf16 pack (no F2FP converts)
__device__ __forceinline__ unsigned pack_x(float f) {   // (lo | hi<<16)
    unsigned u  = __float_as_uint(f);
    unsigned hu = (u + 0x8000u) & 0xFFFF0000u;
    float fl    = f - __uint_as_float(hu);
    unsigned lo = (__float_as_uint(fl) + 0x8000u) >> 16;
    return hu | lo;
}
__device__ __forceinline__ unsigned pack_w(float f) {   // (hi | lo<<16)
    unsigned u  = __float_as_uint(f);
    unsigned hu = (u + 0x8000u) & 0xFFFF0000u;
    float fl    = f - __uint_as_float(hu);
    unsigned lo = (__float_as_uint(fl) + 0x8000u) & 0xFFFF0000u;
    return (hu >> 16) | lo;
}

// merged prep: b < B_ -> NCHW->padded-NHWC transpose slice; b == B_ -> W pack
__global__ void prep_kernel(const float* __restrict__ x,
                            const float* __restrict__ Wm) {
    const int b  = blockIdx.z;
    const int tx = threadIdx.x, ty = threadIdx.y;   // 32 x 8
    if (b < B_) {
        __shared__ unsigned t[32][33];
        const int h  = blockIdx.y;
        const int cb = (blockIdx.x >> 1) * 32;
        const int wb = (blockIdx.x & 1) * 32;
        const int w  = wb + tx;
        if (w < W_) {
#pragma unroll
            for (int i = 0; i < 4; i++) {
                int c = cb + ty + 8 * i;
                t[ty + 8 * i][tx] = pack_x(x[(((size_t)b * C_ + c) * H_ + h) * W_ + w]);
            }
        }
        __syncthreads();
#pragma unroll
        for (int i = 0; i < 4; i++) {
            int wo = wb + ty + 8 * i;
            int co = cb + tx;
            if (wo < W_)
                g_xt[(((size_t)b * HP + h + 1) * WP + wo + 1) * C_ + co] = t[tx][ty + 8 * i];
        }
    } else {
        const int tlin   = ty * 32 + tx;
        const int base   = (blockIdx.y * gridDim.x + blockIdx.x) * 256 + tlin;
        const int stride = gridDim.x * gridDim.y * 256;
        for (int j = base; j < NW_; j += stride) {
            int oc  = j / KDIM;
            int r   = j - oc * KDIM;
            int c   = r / 9;
            int tap = r - c * 9;
            g_wi[oc * KDIM + tap * 128 + c] = pack_w(Wm[j]);
        }
    }
}

// ---- helpers ----
__device__ __forceinline__ unsigned smem_u32(const void* p) {
    return (unsigned)__cvta_generic_to_shared(p);
}
__device__ __forceinline__ unsigned sw128(unsigned off) {
    return off ^ ((off >> 3) & 0x70);
}
__device__ __forceinline__ void cpa16(unsigned dst, const void* src) {
    asm volatile("cp.async.cg.shared.global [%0], [%1], 16;\n"
                 :: "r"(dst), "l"(src));
}
__device__ __forceinline__ void ldsm4(unsigned* r, unsigned addr) {
    asm volatile("ldmatrix.sync.aligned.m8n8.x4.shared.b16 {%0,%1,%2,%3}, [%4];"
                 : "=r"(r[0]), "=r"(r[1]), "=r"(r[2]), "=r"(r[3]) : "r"(addr));
}
__device__ __forceinline__ void mma16816(float* c, const unsigned* a,
                                         unsigned b0, unsigned b1) {
    asm("mma.sync.aligned.m16n8k16.row.col.f32.bf16.bf16.f32 "
        "{%0,%1,%2,%3}, {%4,%5,%6,%7}, {%8,%9}, {%0,%1,%2,%3};"
        : "+f"(c[0]), "+f"(c[1]), "+f"(c[2]), "+f"(c[3])
        : "r"(a[0]), "r"(a[1]), "r"(a[2]), "r"(a[3]), "r"(b0), "r"(b1));
}

// ---- smem layout (bytes) ----
#define SM_BIAS 0
#define SM_TILE 1024
#define T_A     0                // 128 pix * 128B = 16384
#define T_B     16384            // 128 oc * 128B = 16384
#define STG     32768
#define SMEM_TOTAL (SM_TILE + 3 * STG)   // 99328  -> 2 CTAs/SM

__global__ __launch_bounds__(NT, 2)
void conv_hmma_kernel(const float* __restrict__ bias, float* __restrict__ out) {
    extern __shared__ char smem[];
    const int tid  = threadIdx.x;
    const int lane = tid & 31;
    const int wid  = tid >> 5;
    const int m0   = blockIdx.x * BM;
    const int n0   = blockIdx.y * BN;

    ((float*)(smem + SM_BIAS))[tid] = bias[tid];   // NT == OC_

    // ---- A-producer: thread handles 4 pixels x one 16B channel-chunk ----
    const int chA = tid & 7;
    const unsigned* aptr[4];
    unsigned adst[4];
#pragma unroll
    for (int i = 0; i < 4; i++) {
        int pix  = (tid >> 3) + 32 * i;
        int p    = m0 + pix;
        int bimg = p / HW_;
        int hw   = p - bimg * HW_;
        int h    = hw / W_;
        int w    = hw - h * W_;
        aptr[i]  = g_xt + (((size_t)bimg * HP + h) * WP + w) * C_ + chA * 4;
        adst[i]  = (unsigned)(pix * 128 + chA * 16);
    }

    auto load_stage = [&](int s, int slot) {
        char* stg = smem + SM_TILE + slot * STG;
        int tap = s >> 2;
        int c0  = (s & 3) << 5;
        int kh  = tap / 3;
        int kw  = tap - 3 * kh;
        const size_t soff = ((size_t)kh * WP + kw) * C_ + c0;
        const unsigned abase_s = smem_u32(stg + T_A);
#pragma unroll
        for (int i = 0; i < 4; i++)
            cpa16(abase_s + sw128(adst[i]), aptr[i] + soff);
#pragma unroll
        for (int i = 0; i < 4; i++) {
            int q  = tid + NT * i;
            int oc = q >> 3;
            int ch = q & 7;
            const unsigned* bsrc = g_wi + (size_t)(n0 + oc) * KDIM + s * BKW + ch * 4;
            cpa16(smem_u32(stg + T_B + sw128((unsigned)(oc * 128 + ch * 16))), bsrc);
        }
        asm volatile("cp.async.commit_group;\n");
    };

    // warp tiling: 2 (M) x 4 (N) warps, warp tile 64 x 32
    const int wm = (wid & 1) * 64;
    const int wn = (wid >> 1) * 32;

    float acc[4][4][4];
#pragma unroll
    for (int a = 0; a < 4; a++)
#pragma unroll
        for (int b = 0; b < 4; b++)
#pragma unroll
            for (int cq = 0; cq < 4; cq++) acc[a][b][cq] = 0.0f;

    load_stage(0, 0);
    load_stage(1, 1);

    int slot = 0, slot2 = 2;
    for (int s = 0; s < NSTAGE; s++) {
        asm volatile("cp.async.wait_group 1;\n");
        __syncthreads();

        if (s + 2 < NSTAGE) load_stage(s + 2, slot2);
        else asm volatile("cp.async.commit_group;\n");

        char* stg = smem + SM_TILE + slot * STG;
        const unsigned abase = smem_u32(stg + T_A);
        const unsigned bbase = smem_u32(stg + T_B);

#pragma unroll
        for (int pp = 0; pp < 2; pp++) {
            unsigned afrE[4][4], afrO[4][4];
#pragma unroll
            for (int mi = 0; mi < 4; mi++) {
                int row = wm + mi * 16 + (lane & 15);
                unsigned base = (unsigned)(row * 128 + (lane >> 4) * 16);
                ldsm4(afrE[mi], abase + sw128(base + (2 * pp + 0) * 32));
                ldsm4(afrO[mi], abase + sw128(base + (2 * pp + 1) * 32));
            }
            unsigned ahi[4][4];
#pragma unroll
            for (int mi = 0; mi < 4; mi++) {
                ahi[mi][0] = __byte_perm(afrE[mi][0], afrE[mi][2], 0x7632);
                ahi[mi][1] = __byte_perm(afrE[mi][1], afrE[mi][3], 0x7632);
                ahi[mi][2] = __byte_perm(afrO[mi][0], afrO[mi][2], 0x7632);
                ahi[mi][3] = __byte_perm(afrO[mi][1], afrO[mi][3], 0x7632);
            }
#pragma unroll
            for (int ni = 0; ni < 2; ni++) {
                unsigned bE[4], bO[4];
                int g   = lane >> 3;
                int r   = lane & 7;
                int ocl = wn + ni * 16 + ((g & 2) ? 8 : 0) + r;
                unsigned base = (unsigned)(ocl * 128 + (g & 1) * 16);
                ldsm4(bE, bbase + sw128(base + (2 * pp + 0) * 32));
                ldsm4(bO, bbase + sw128(base + (2 * pp + 1) * 32));
                unsigned bh0 = __byte_perm(bE[0], bE[1], 0x5410);
                unsigned bh1 = __byte_perm(bO[0], bO[1], 0x5410);
                unsigned bh2 = __byte_perm(bE[2], bE[3], 0x5410);
                unsigned bh3 = __byte_perm(bO[2], bO[3], 0x5410);
#pragma unroll
                for (int mi = 0; mi < 4; mi++)
                    mma16816(acc[mi][ni * 2 + 0], afrE[mi], bE[0], bE[1]);
#pragma unroll
                for (int mi = 0; mi < 4; mi++)
                    mma16816(acc[mi][ni * 2 + 1], afrE[mi], bE[2], bE[3]);
#pragma unroll
                for (int mi = 0; mi < 4; mi++)
                    mma16816(acc[mi][ni * 2 + 0], afrO[mi], bO[0], bO[1]);
#pragma unroll
                for (int mi = 0; mi < 4; mi++)
                    mma16816(acc[mi][ni * 2 + 1], afrO[mi], bO[2], bO[3]);
#pragma unroll
                for (int mi = 0; mi < 4; mi++)
                    mma16816(acc[mi][ni * 2 + 0], ahi[mi], bh0, bh1);
#pragma unroll
                for (int mi = 0; mi < 4; mi++)
                    mma16816(acc[mi][ni * 2 + 1], ahi[mi], bh2, bh3);
            }
        }

        slot  = (slot  == 2) ? 0 : slot  + 1;
        slot2 = (slot2 == 2) ? 0 : slot2 + 1;
    }

    __syncthreads();

    // ---- epilogue: transpose through smem, coalesced float4 stores ----
    float* Cs = (float*)(smem + SM_TILE);   // [oc 128][pix 128] = 64KB
#pragma unroll
    for (int mi = 0; mi < 4; mi++)
#pragma unroll
        for (int nq = 0; nq < 4; nq++) {
            int r0 = wm + mi * 16 + (lane >> 2);
            int cb = wn + nq * 8 + (lane & 3) * 2;
            Cs[(cb + 0) * BM + r0]     = acc[mi][nq][0];
            Cs[(cb + 1) * BM + r0]     = acc[mi][nq][1];
            Cs[(cb + 0) * BM + r0 + 8] = acc[mi][nq][2];
            Cs[(cb + 1) * BM + r0 + 8] = acc[mi][nq][3];
        }
    __syncthreads();

    const float* bs = (const float*)(smem + SM_BIAS);
    for (int g = tid; g < BN * (BM / 4); g += NT) {
        int ocl  = g >> 5;
        int pixl = (g & 31) * 4;
        int pp   = m0 + pixl;
        int bi   = pp / HW_;
        int off  = pp - bi * HW_;
        int oc   = n0 + ocl;
        float4 v = *(const float4*)&Cs[ocl * BM + pixl];
        float bv = bs[oc];
        v.x += bv; v.y += bv; v.z += bv; v.w += bv;
        *(float4*)(out + (size_t)bi * OC_ * HW_ + (size_t)oc * HW_ + off) = v;
    }
}

extern "C" void kernel_launch(void* const* d_in, const int* in_sizes, int n_in,
                              void* d_out, int out_size) {
    const float* x  = (const float*)d_in[0];
    const float* Wm = (const float*)d_in[1];
    const float* bb = (const float*)d_in[2];
    float* out      = (float*)d_out;

    dim3 pgrid(8, H_, B_ + 1);             // z = B_ slice does W pack
    prep_kernel<<<pgrid, dim3(32, 8)>>>(x, Wm);

    cudaFuncSetAttribute(conv_hmma_kernel,
                         cudaFuncAttributeMaxDynamicSharedMemorySize, SMEM_TOTAL);
    dim3 grid(M_ / BM, OC_ / BN);   // 784 x 2
    conv_hmma_kernel<<<grid, NT, SMEM_TOTAL>>>(bb, out);
}